// round 16
// baseline (speedup 1.0000x reference)
#include <cuda_runtime.h>

// Problem constants
#define IN_F    2048
#define OUT_F   4096
#define BATCHN  131072
#define IN_F4   (IN_F / 4)        // 512 float4 columns

// Fused-kernel block layout (producer bids < consumer bids; low bids are
// wave-1 resident deterministically => deadlock-free spins).
#define NFOLD    16               // folder blocks (bids 0..15)
#define BID_BIAS 16
#define NRED     512              // weight reducers (bids 17..528), 16 rows each
#define BID_RED0 17
#define BID_GEMV0 (BID_RED0 + NRED)          // 529
#define NGEMV    (BATCHN / 8)                // 16384
#define GRID_TOTAL (BID_GEMV0 + NGEMV)       // 16913

#define NSLICE   256              // 4096 rows / 16 rows per reducer slice

// Scratch globals (allocation-free, fully rewritten every launch =>
// graph-replay deterministic).
__device__ float4 g_partial4[NSLICE * IN_F4];   // 2 MiB
__device__ float  g_wsum[IN_F];
__device__ float  g_bsum;
__device__ int    g_red_done;     // -> NRED
__device__ int    g_fold_done;    // -> NFOLD + 1

__global__ void init_kernel() {
    g_red_done  = 0;
    g_fold_done = 0;
}

// Forced-MLP vector load: inline asm pins 4 float regs per load, so ptxas
// cannot collapse a batch into a short-register rolling chain.
__device__ __forceinline__ float4 ldg_nc_v4(const float4* p) {
    float4 v;
    asm volatile("ld.global.nc.v4.f32 {%0,%1,%2,%3}, [%4];"
                 : "=f"(v.x), "=f"(v.y), "=f"(v.z), "=f"(v.w)
                 : "l"(p));
    return v;
}

// ---------------------------------------------------------------------------
// NOTE: no minBlocks clause — the forced __launch_bounds__(256,5) binary
// failed the container twice (suspected spill pathology). Register demand is
// instead reduced naturally: preload 4 (not 8) float4, reducer batches of 4.
// If ptxas lands <= 52 regs we get 5 blocks/SM for free.
__global__ __launch_bounds__(256) void fused_kernel(const float4* __restrict__ w4,
                                                    const float*  __restrict__ x,
                                                    const float*  __restrict__ bias,
                                                    float* __restrict__ out) {
    __shared__ float4 sw[IN_F4];      // 8 KB
    const int tid = threadIdx.x;
    const int bid = blockIdx.x;

    // ======================== GEMV blocks (hot path) ========================
    if (bid >= BID_GEMV0) {
        const int gvb  = bid - BID_GEMV0;
        const int warp = tid >> 5;
        const int lane = tid & 31;
        const int row  = gvb * 8 + warp;
        const float4* xr = reinterpret_cast<const float4*>(x + (size_t)row * IN_F);

        // Preload 4 float4 of REAL x data before waiting (16 regs live).
        // Register-destined, single-use: overlaps the weight reduction
        // without polluting L2.
        float4 xa0 = xr[0 * 32 + lane];
        float4 xa1 = xr[1 * 32 + lane];
        float4 xa2 = xr[2 * 32 + lane];
        float4 xa3 = xr[3 * 32 + lane];

        // Wait for w_sum + b_sum (loads above stay in flight).
        if (tid == 0) {
            int backoff = 32;
            while (*(volatile int*)&g_fold_done != (NFOLD + 1)) {
                __nanosleep(backoff);
                if (backoff < 256) backoff <<= 1;
            }
            __threadfence();
        }
        __syncthreads();

        // Stage w_sum into shared.
        #pragma unroll
        for (int i = 0; i < IN_F4 / 256; ++i) {
            sw[i * 256 + tid] = reinterpret_cast<const float4*>(g_wsum)[i * 256 + tid];
        }
        __syncthreads();
        const float bsum = g_bsum;

        float acc = 0.0f;
        {   // preloaded quarter
            float4 wv;
            wv = sw[0 * 32 + lane];
            acc += xa0.x * wv.x + xa0.y * wv.y + xa0.z * wv.z + xa0.w * wv.w;
            wv = sw[1 * 32 + lane];
            acc += xa1.x * wv.x + xa1.y * wv.y + xa1.z * wv.z + xa1.w * wv.w;
            wv = sw[2 * 32 + lane];
            acc += xa2.x * wv.x + xa2.y * wv.y + xa2.z * wv.z + xa2.w * wv.w;
            wv = sw[3 * 32 + lane];
            acc += xa3.x * wv.x + xa3.y * wv.y + xa3.z * wv.z + xa3.w * wv.w;
        }
        #pragma unroll
        for (int i = 4; i < 16; ++i) {          // streamed remainder
            const float4 xv = xr[i * 32 + lane];
            const float4 wv = sw[i * 32 + lane];
            acc += xv.x * wv.x + xv.y * wv.y + xv.z * wv.z + xv.w * wv.w;
        }
        #pragma unroll
        for (int off = 16; off > 0; off >>= 1) {
            acc += __shfl_xor_sync(0xFFFFFFFFu, acc, off);
        }
        if (lane == 0) out[row] = acc + bsum;
        return;
    }

    // ======================== Weight reducer blocks ========================
    if (bid >= BID_RED0) {
        const int r  = bid - BID_RED0;
        const int cg = r & 1;              // column group
        const int s  = r >> 1;             // 16-row slice
        const int c  = cg * 256 + tid;
        const float4* wp = w4 + (size_t)(s * 16) * IN_F4 + c;

        float4 acc = make_float4(0.f, 0.f, 0.f, 0.f);
        #pragma unroll
        for (int b = 0; b < 4; ++b) {
            // 4 asm loads with pinned destination registers (16 regs live).
            const float4* p = wp + (size_t)(b * 4) * IN_F4;
            float4 t0 = ldg_nc_v4(p + 0 * IN_F4);
            float4 t1 = ldg_nc_v4(p + 1 * IN_F4);
            float4 t2 = ldg_nc_v4(p + 2 * IN_F4);
            float4 t3 = ldg_nc_v4(p + 3 * IN_F4);
            t0.x += t1.x; t0.y += t1.y; t0.z += t1.z; t0.w += t1.w;
            t2.x += t3.x; t2.y += t3.y; t2.z += t3.z; t2.w += t3.w;
            acc.x += t0.x + t2.x;
            acc.y += t0.y + t2.y;
            acc.z += t0.z + t2.z;
            acc.w += t0.w + t2.w;
        }
        g_partial4[s * IN_F4 + c] = acc;
        __threadfence();
        __syncthreads();
        if (tid == 0) atomicAdd(&g_red_done, 1);
        return;
    }

    // ======================== Bias block ========================
    if (bid == BID_BIAS) {
        __shared__ float red[256];
        float s = 0.0f;
        #pragma unroll
        for (int i = 0; i < OUT_F / 256; ++i) s += bias[i * 256 + tid];
        red[tid] = s;
        __syncthreads();
        #pragma unroll
        for (int stride = 128; stride > 0; stride >>= 1) {
            if (tid < stride) red[tid] += red[tid + stride];
            __syncthreads();
        }
        if (tid == 0) {
            g_bsum = red[0];
            __threadfence();
            atomicAdd(&g_fold_done, 1);
        }
        return;
    }

    // ======================== Folder blocks (bids 0..15) ========================
    {
        if (tid == 0) {
            int backoff = 32;
            while (*(volatile int*)&g_red_done != NRED) {
                __nanosleep(backoff);
                if (backoff < 256) backoff <<= 1;
            }
            __threadfence();
        }
        __syncthreads();

        const int lane = tid & 31;
        const int wrp  = tid >> 5;           // 8 warps = 8 slice groups
        const int col  = bid * 32 + lane;    // this block's 32 float4 columns

        float4 acc = make_float4(0.f, 0.f, 0.f, 0.f);
        #pragma unroll 8
        for (int j = 0; j < 32; ++j) {       // slices p = wrp + 8*j
            const float4 v = g_partial4[(wrp + 8 * j) * IN_F4 + col];
            acc.x += v.x; acc.y += v.y; acc.z += v.z; acc.w += v.w;
        }

        float4* sh = sw;                     // 8*32 float4 = 4 KB
        sh[wrp * 32 + lane] = acc;
        __syncthreads();
        if (wrp == 0) {
            float4 t = sh[lane];
            #pragma unroll
            for (int p = 1; p < 8; ++p) {
                const float4 v = sh[p * 32 + lane];
                t.x += v.x; t.y += v.y; t.z += v.z; t.w += v.w;
            }
            reinterpret_cast<float4*>(g_wsum)[col] = t;
            __threadfence();
        }
        __syncthreads();
        if (tid == 0) atomicAdd(&g_fold_done, 1);
        return;
    }
}

// ---------------------------------------------------------------------------
extern "C" void kernel_launch(void* const* d_in, const int* in_sizes, int n_in,
                              void* d_out, int out_size) {
    const float* x      = (const float*)d_in[0];  // (131072, 2048)
    const float* weight = (const float*)d_in[1];  // (4096, 2048)
    const float* bias   = (const float*)d_in[2];  // (4096,)
    float* out = (float*)d_out;                   // (131072, 1)

    (void)in_sizes; (void)n_in; (void)out_size;

    init_kernel<<<1, 1>>>();
    fused_kernel<<<GRID_TOTAL, 256>>>(reinterpret_cast<const float4*>(weight),
                                      x, bias, out);
}

// round 17
// speedup vs baseline: 1.0190x; 1.0190x over previous
#include <cuda_runtime.h>

// Problem constants
#define IN_F    2048
#define OUT_F   4096
#define BATCHN  131072
#define IN_F4   (IN_F / 4)        // 512 float4 columns

// Fused-kernel block layout (producer bids < consumer bids; low bids are
// wave-1 resident deterministically => deadlock-free spins).
#define NFOLD    16               // folder blocks (bids 0..15)
#define BID_BIAS 16
#define NRED     512              // weight reducers (bids 17..528), 16 rows each
#define BID_RED0 17
#define BID_GEMV0 (BID_RED0 + NRED)          // 529
#define NGEMV    (BATCHN / 8)                // 16384
#define GRID_TOTAL (BID_GEMV0 + NGEMV)       // 16913

#define NSLICE   256              // 4096 rows / 16 rows per reducer slice

// Scratch globals (allocation-free, fully rewritten every launch =>
// graph-replay deterministic).
__device__ float4 g_partial4[NSLICE * IN_F4];   // 2 MiB
__device__ float  g_wsum[IN_F];
__device__ float  g_bsum;
__device__ int    g_red_done;     // -> NRED
__device__ int    g_fold_done;    // -> NFOLD + 1

__global__ void init_kernel() {
    g_red_done  = 0;
    g_fold_done = 0;
}

// Forced-MLP vector load: inline asm pins 4 float regs per load, so ptxas
// cannot collapse a batch into a short-register rolling chain.
__device__ __forceinline__ float4 ldg_nc_v4(const float4* p) {
    float4 v;
    asm volatile("ld.global.nc.v4.f32 {%0,%1,%2,%3}, [%4];"
                 : "=f"(v.x), "=f"(v.y), "=f"(v.z), "=f"(v.w)
                 : "l"(p));
    return v;
}

// ---------------------------------------------------------------------------
// Register budget: gemv path keeps the PROVEN 8-float4 preload (R13: 7.02 TB/s
// vs R16's 4-preload 6.88 TB/s); the reducer path gives back its registers
// (4-load batches; reducer speed is fully overlapped and irrelevant).
// Expected regs ~50-54: if <=52 we also get 5 blocks/SM on top.
__global__ __launch_bounds__(256) void fused_kernel(const float4* __restrict__ w4,
                                                    const float*  __restrict__ x,
                                                    const float*  __restrict__ bias,
                                                    float* __restrict__ out) {
    __shared__ float4 sw[IN_F4];      // 8 KB
    const int tid = threadIdx.x;
    const int bid = blockIdx.x;

    // ======================== GEMV blocks (hot path) ========================
    if (bid >= BID_GEMV0) {
        const int gvb  = bid - BID_GEMV0;
        const int warp = tid >> 5;
        const int lane = tid & 31;
        const int row  = gvb * 8 + warp;
        const float4* xr = reinterpret_cast<const float4*>(x + (size_t)row * IN_F);

        // Preload 8 float4 of REAL x data before waiting (32 regs live).
        // Register-destined, single-use: overlaps the weight reduction
        // without polluting L2. (8-deep proven better than 4-deep: R13 vs R16.)
        float4 xa[8];
        #pragma unroll
        for (int i = 0; i < 8; ++i) {
            xa[i] = xr[i * 32 + lane];
        }

        // Wait for w_sum + b_sum (loads above stay in flight).
        if (tid == 0) {
            int backoff = 32;
            while (*(volatile int*)&g_fold_done != (NFOLD + 1)) {
                __nanosleep(backoff);
                if (backoff < 256) backoff <<= 1;
            }
            __threadfence();
        }
        __syncthreads();

        // Stage w_sum into shared.
        #pragma unroll
        for (int i = 0; i < IN_F4 / 256; ++i) {
            sw[i * 256 + tid] = reinterpret_cast<const float4*>(g_wsum)[i * 256 + tid];
        }
        __syncthreads();
        const float bsum = g_bsum;

        float acc = 0.0f;
        #pragma unroll
        for (int i = 0; i < 8; ++i) {           // preloaded half
            const float4 wv = sw[i * 32 + lane];
            acc += xa[i].x * wv.x + xa[i].y * wv.y + xa[i].z * wv.z + xa[i].w * wv.w;
        }
        #pragma unroll
        for (int i = 8; i < 16; ++i) {          // streamed half
            const float4 xv = xr[i * 32 + lane];
            const float4 wv = sw[i * 32 + lane];
            acc += xv.x * wv.x + xv.y * wv.y + xv.z * wv.z + xv.w * wv.w;
        }
        #pragma unroll
        for (int off = 16; off > 0; off >>= 1) {
            acc += __shfl_xor_sync(0xFFFFFFFFu, acc, off);
        }
        if (lane == 0) out[row] = acc + bsum;
        return;
    }

    // ======================== Weight reducer blocks ========================
    if (bid >= BID_RED0) {
        const int r  = bid - BID_RED0;
        const int cg = r & 1;              // column group
        const int s  = r >> 1;             // 16-row slice
        const int c  = cg * 256 + tid;
        const float4* wp = w4 + (size_t)(s * 16) * IN_F4 + c;

        float4 acc = make_float4(0.f, 0.f, 0.f, 0.f);
        #pragma unroll
        for (int b = 0; b < 4; ++b) {
            // 4 asm loads with pinned destination registers (16 regs live).
            const float4* p = wp + (size_t)(b * 4) * IN_F4;
            float4 t0 = ldg_nc_v4(p + 0 * IN_F4);
            float4 t1 = ldg_nc_v4(p + 1 * IN_F4);
            float4 t2 = ldg_nc_v4(p + 2 * IN_F4);
            float4 t3 = ldg_nc_v4(p + 3 * IN_F4);
            t0.x += t1.x; t0.y += t1.y; t0.z += t1.z; t0.w += t1.w;
            t2.x += t3.x; t2.y += t3.y; t2.z += t3.z; t2.w += t3.w;
            acc.x += t0.x + t2.x;
            acc.y += t0.y + t2.y;
            acc.z += t0.z + t2.z;
            acc.w += t0.w + t2.w;
        }
        g_partial4[s * IN_F4 + c] = acc;
        __threadfence();
        __syncthreads();
        if (tid == 0) atomicAdd(&g_red_done, 1);
        return;
    }

    // ======================== Bias block ========================
    if (bid == BID_BIAS) {
        __shared__ float red[256];
        float s = 0.0f;
        #pragma unroll
        for (int i = 0; i < OUT_F / 256; ++i) s += bias[i * 256 + tid];
        red[tid] = s;
        __syncthreads();
        #pragma unroll
        for (int stride = 128; stride > 0; stride >>= 1) {
            if (tid < stride) red[tid] += red[tid + stride];
            __syncthreads();
        }
        if (tid == 0) {
            g_bsum = red[0];
            __threadfence();
            atomicAdd(&g_fold_done, 1);
        }
        return;
    }

    // ======================== Folder blocks (bids 0..15) ========================
    {
        if (tid == 0) {
            int backoff = 32;
            while (*(volatile int*)&g_red_done != NRED) {
                __nanosleep(backoff);
                if (backoff < 256) backoff <<= 1;
            }
            __threadfence();
        }
        __syncthreads();

        const int lane = tid & 31;
        const int wrp  = tid >> 5;           // 8 warps = 8 slice groups
        const int col  = bid * 32 + lane;    // this block's 32 float4 columns

        float4 acc = make_float4(0.f, 0.f, 0.f, 0.f);
        #pragma unroll 8
        for (int j = 0; j < 32; ++j) {       // slices p = wrp + 8*j
            const float4 v = g_partial4[(wrp + 8 * j) * IN_F4 + col];
            acc.x += v.x; acc.y += v.y; acc.z += v.z; acc.w += v.w;
        }

        float4* sh = sw;                     // 8*32 float4 = 4 KB
        sh[wrp * 32 + lane] = acc;
        __syncthreads();
        if (wrp == 0) {
            float4 t = sh[lane];
            #pragma unroll
            for (int p = 1; p < 8; ++p) {
                const float4 v = sh[p * 32 + lane];
                t.x += v.x; t.y += v.y; t.z += v.z; t.w += v.w;
            }
            reinterpret_cast<float4*>(g_wsum)[col] = t;
            __threadfence();
        }
        __syncthreads();
        if (tid == 0) atomicAdd(&g_fold_done, 1);
        return;
    }
}

// ---------------------------------------------------------------------------
extern "C" void kernel_launch(void* const* d_in, const int* in_sizes, int n_in,
                              void* d_out, int out_size) {
    const float* x      = (const float*)d_in[0];  // (131072, 2048)
    const float* weight = (const float*)d_in[1];  // (4096, 2048)
    const float* bias   = (const float*)d_in[2];  // (4096,)
    float* out = (float*)d_out;                   // (131072, 1)

    (void)in_sizes; (void)n_in; (void)out_size;

    init_kernel<<<1, 1>>>();
    fused_kernel<<<GRID_TOTAL, 256>>>(reinterpret_cast<const float4*>(weight),
                                      x, bias, out);
}